// round 14
// baseline (speedup 1.0000x reference)
#include <cuda_runtime.h>
#include <cuda_bf16.h>
#include <stdint.h>
#include <math.h>

#define Q_LEN   1024
#define KV_LEN  6404
#define KV_PAD  6464
#define HIDDEN  4096
#define NH      32
#define NKVH    8
#define HD      128
#define QKV_LDB 6144
#define KV_N    2048
#define ATTN_SCALE 0.08838834764831845f

// ---------------- scratch ----------------
__device__ float g_q[Q_LEN * HIDDEN];
__device__ float g_kv[KV_LEN * KV_N];

__device__ __nv_bfloat16 g_hid_hi[Q_LEN * HIDDEN];
__device__ __nv_bfloat16 g_hid_lo[Q_LEN * HIDDEN];
__device__ __nv_bfloat16 g_cross_hi[KV_LEN * HIDDEN];
__device__ __nv_bfloat16 g_cross_lo[KV_LEN * HIDDEN];
__device__ __nv_bfloat16 g_wqkvT_hi[QKV_LDB * HIDDEN];
__device__ __nv_bfloat16 g_wqkvT_lo[QKV_LDB * HIDDEN];
__device__ __nv_bfloat16 g_woT_hi[HIDDEN * HIDDEN];
__device__ __nv_bfloat16 g_woT_lo[HIDDEN * HIDDEN];
__device__ __nv_bfloat16 g_qhi[Q_LEN * HIDDEN];
__device__ __nv_bfloat16 g_qlo[Q_LEN * HIDDEN];
__device__ __nv_bfloat16 g_khi[KV_LEN * (NKVH * HD)];
__device__ __nv_bfloat16 g_klo[KV_LEN * (NKVH * HD)];
__device__ __nv_bfloat16 g_vthi[NKVH * HD * KV_PAD];
__device__ __nv_bfloat16 g_vtlo[NKVH * HD * KV_PAD];
__device__ __nv_bfloat16 g_attnhi[Q_LEN * HIDDEN];
__device__ __nv_bfloat16 g_attnlo[Q_LEN * HIDDEN];

__device__ __forceinline__ void split2(float x, float y, unsigned& hi, unsigned& lo)
{
    __nv_bfloat16 hx = __float2bfloat16(x), hy = __float2bfloat16(y);
    float lx = x - __bfloat162float(hx), ly = y - __bfloat162float(hy);
    __nv_bfloat16 lxb = __float2bfloat16(lx), lyb = __float2bfloat16(ly);
    hi = (unsigned)__bfloat16_as_ushort(hx) | ((unsigned)__bfloat16_as_ushort(hy) << 16);
    lo = (unsigned)__bfloat16_as_ushort(lxb) | ((unsigned)__bfloat16_as_ushort(lyb) << 16);
}

__device__ __forceinline__ uint32_t smem_u32(const void* p)
{
    uint32_t a;
    asm("{ .reg .u64 t; cvta.to.shared.u64 t, %1; cvt.u32.u64 %0, t; }"
        : "=r"(a) : "l"(p));
    return a;
}
#define CP16(dst, src, n) \
    asm volatile("cp.async.cg.shared.global [%0], [%1], 16, %2;" \
                 :: "r"(dst), "l"(src), "r"(n))
#define CP_COMMIT() asm volatile("cp.async.commit_group;" ::: "memory")
#define CP_WAIT1()  asm volatile("cp.async.wait_group 1;" ::: "memory")

#define MMA_BF16(d, a, b)                                                      \
    asm volatile(                                                              \
        "mma.sync.aligned.m16n8k16.row.col.f32.bf16.bf16.f32 "                 \
        "{%0,%1,%2,%3},{%4,%5,%6,%7},{%8,%9},{%0,%1,%2,%3};"                   \
        : "+f"((d)[0]), "+f"((d)[1]), "+f"((d)[2]), "+f"((d)[3])               \
        : "r"((a)[0]), "r"((a)[1]), "r"((a)[2]), "r"((a)[3]),                  \
          "r"((b)[0]), "r"((b)[1]))

#define LDSM4(r, addr)                                                         \
    asm volatile(                                                              \
        "ldmatrix.sync.aligned.m8n8.x4.shared.b16 {%0,%1,%2,%3}, [%4];"        \
        : "=r"((r)[0]), "=r"((r)[1]), "=r"((r)[2]), "=r"((r)[3])               \
        : "r"(addr))

// ---------------- bf16x3 GEMM, block 128x256 (R12, unchanged) ----------------
#define GA_BUF   (128 * 128)
#define GBB_BUF  (256 * 128)
#define GS_AH    0
#define GS_AL    GA_BUF
#define GS_BH    (2 * GA_BUF)
#define GS_BL    (2 * GA_BUF + GBB_BUF)
#define GB_STAGE (2 * GA_BUF + 2 * GBB_BUF)
#define GB_SMEM  (2 * GB_STAGE)

__global__ void __launch_bounds__(256, 1) gemm_bf16x3(
    const __nv_bfloat16* __restrict__ Ahi, const __nv_bfloat16* __restrict__ Alo,
    const __nv_bfloat16* __restrict__ Bthi, const __nv_bfloat16* __restrict__ Btlo,
    float* __restrict__ C, int M, int ldc)
{
    extern __shared__ char smg[];
    const uint32_t sb = smem_u32(smg);
    const int tid  = threadIdx.x;
    const int warp = tid >> 5, lane = tid & 31;
    const int g = lane >> 2, tig = lane & 3;
    const int wm = warp & 1, wn = warp >> 1;
    const int row0 = blockIdx.y * 128, col0 = blockIdx.x * 256;
    const int rowbase = wm * 64, colbase = wn * 64;
    const int K = HIDDEN;
    const int nck = K / 64;

    const int a_row_in = lane & 15;
    const int a_ckb    = lane >> 4;
    const int b_row_in = (((lane >> 4) & 1) << 3) + (lane & 7);
    const int b_ckb    = (lane >> 3) & 1;

    float acc[4][8][4];
#pragma unroll
    for (int i = 0; i < 4; i++)
#pragma unroll
        for (int j = 0; j < 8; j++)
#pragma unroll
            for (int t = 0; t < 4; t++) acc[i][j][t] = 0.f;

    auto load_chunk = [&](int ck, int st) {
        const uint32_t stb = sb + st * GB_STAGE;
        const int k0 = ck * 64;
#pragma unroll
        for (int i = 0; i < 4; i++) {
            int idx = tid + i * 256;
            int r = idx >> 3, c = idx & 7;
            uint32_t soff = (uint32_t)(r * 128 + ((c ^ (r & 7)) * 16));
            int gr = row0 + r;
            int ok = (gr < M) ? 16 : 0;
            int grc = (gr < M) ? gr : 0;
            size_t aoff = (size_t)grc * K + k0 + c * 8;
            CP16(stb + GS_AH + soff, Ahi + aoff, ok);
            CP16(stb + GS_AL + soff, Alo + aoff, ok);
        }
#pragma unroll
        for (int i = 0; i < 8; i++) {
            int idx = tid + i * 256;
            int r = idx >> 3, c = idx & 7;
            uint32_t soff = (uint32_t)(r * 128 + ((c ^ (r & 7)) * 16));
            size_t boff = (size_t)(col0 + r) * K + k0 + c * 8;
            CP16(stb + GS_BH + soff, Bthi + boff, 16);
            CP16(stb + GS_BL + soff, Btlo + boff, 16);
        }
    };

    load_chunk(0, 0);
    CP_COMMIT();

    for (int ck = 0; ck < nck; ck++) {
        const int st = ck & 1;
        if (ck + 1 < nck) load_chunk(ck + 1, st ^ 1);
        CP_COMMIT();
        CP_WAIT1();
        __syncthreads();

        const uint32_t stb = sb + st * GB_STAGE;

#pragma unroll
        for (int ks = 0; ks < 4; ks++) {
            unsigned ah[4][4], al[4][4], bb[8][2], bfr[4];
#pragma unroll
            for (int am = 0; am < 4; am++) {
                int row = rowbase + am * 16 + a_row_in;
                int ck4 = (2 * ks + a_ckb) ^ (row & 7);
                uint32_t addr = stb + (uint32_t)(row * 128 + ck4 * 16);
                LDSM4(ah[am], addr);
                LDSM4(al[am], addr + GA_BUF);
            }
#pragma unroll
            for (int p = 0; p < 4; p++) {
                int row = colbase + p * 16 + b_row_in;
                int ck4 = (2 * ks + b_ckb) ^ (row & 7);
                uint32_t addr = stb + GS_BH + (uint32_t)(row * 128 + ck4 * 16);
                LDSM4(bfr, addr);
                bb[2 * p][0] = bfr[0]; bb[2 * p][1] = bfr[1];
                bb[2 * p + 1][0] = bfr[2]; bb[2 * p + 1][1] = bfr[3];
            }
#pragma unroll
            for (int am = 0; am < 4; am++)
#pragma unroll
                for (int an = 0; an < 8; an++) MMA_BF16(acc[am][an], ah[am], bb[an]);
#pragma unroll
            for (int am = 0; am < 4; am++)
#pragma unroll
                for (int an = 0; an < 8; an++) MMA_BF16(acc[am][an], al[am], bb[an]);
#pragma unroll
            for (int p = 0; p < 4; p++) {
                int row = colbase + p * 16 + b_row_in;
                int ck4 = (2 * ks + b_ckb) ^ (row & 7);
                uint32_t addr = stb + GS_BL + (uint32_t)(row * 128 + ck4 * 16);
                LDSM4(bfr, addr);
                bb[2 * p][0] = bfr[0]; bb[2 * p][1] = bfr[1];
                bb[2 * p + 1][0] = bfr[2]; bb[2 * p + 1][1] = bfr[3];
            }
#pragma unroll
            for (int am = 0; am < 4; am++)
#pragma unroll
                for (int an = 0; an < 8; an++) MMA_BF16(acc[am][an], ah[am], bb[an]);
        }
        __syncthreads();
    }

#pragma unroll
    for (int am = 0; am < 4; am++) {
#pragma unroll
        for (int an = 0; an < 8; an++) {
            int r = row0 + rowbase + am * 16 + g;
            int c = col0 + colbase + an * 8 + tig * 2;
            if (r < M)
                *(float2*)(C + (size_t)r * ldc + c) =
                    make_float2(acc[am][an][0], acc[am][an][1]);
            if (r + 8 < M)
                *(float2*)(C + (size_t)(r + 8) * ldc + c) =
                    make_float2(acc[am][an][2], acc[am][an][3]);
        }
    }
}

// ---------------- fused activation split ----------------
__global__ void split_acts(const float* __restrict__ hid, const float* __restrict__ cross)
{
    const int nh = Q_LEN * HIDDEN / 4;
    const int nc = KV_LEN * HIDDEN / 4;
    int i = blockIdx.x * blockDim.x + threadIdx.x;
    if (i >= nh + nc) return;
    const float4* src;
    __nv_bfloat16 *hi, *lo;
    int j;
    if (i < nh) { src = (const float4*)hid;   hi = g_hid_hi;   lo = g_hid_lo;   j = i; }
    else        { src = (const float4*)cross; hi = g_cross_hi; lo = g_cross_lo; j = i - nh; }
    float4 v = src[j];
    uint2 uh, ul;
    split2(v.x, v.y, uh.x, ul.x);
    split2(v.z, v.w, uh.y, ul.y);
    ((uint2*)hi)[j] = uh;
    ((uint2*)lo)[j] = ul;
}

// ---------------- fp32 [R][C] -> bf16 hi/lo [C][R] ----------------
__global__ void wtrans_split(const float* __restrict__ w,
                             __nv_bfloat16* __restrict__ hi,
                             __nv_bfloat16* __restrict__ lo, int R, int C)
{
    __shared__ float t[32][33];
    int tx = threadIdx.x, ty = threadIdx.y;
    int r0 = blockIdx.y * 32, c0 = blockIdx.x * 32;
#pragma unroll
    for (int i = 0; i < 4; i++)
        t[ty + 8 * i][tx] = w[(size_t)(r0 + ty + 8 * i) * C + c0 + tx];
    __syncthreads();
#pragma unroll
    for (int i = 0; i < 4; i++) {
        float v = t[tx][ty + 8 * i];
        __nv_bfloat16 hb = __float2bfloat16(v);
        __nv_bfloat16 lb = __float2bfloat16(v - __bfloat162float(hb));
        size_t off = (size_t)(c0 + ty + 8 * i) * R + r0 + tx;
        hi[off] = hb; lo[off] = lb;
    }
}

// ---------------- V transpose+split ----------------
__global__ void vtrans_split(const float* __restrict__ kv)
{
    __shared__ float t[32][33];
    int tx = threadIdx.x, ty = threadIdx.y;
    int kv0 = blockIdx.x * 32, d0 = blockIdx.y * 32, kvh = blockIdx.z;
#pragma unroll
    for (int i = 0; i < 4; i++) {
        int r = kv0 + ty + 8 * i;
        t[ty + 8 * i][tx] = (r < KV_LEN)
            ? kv[(size_t)r * KV_N + NKVH * HD + kvh * HD + d0 + tx] : 0.f;
    }
    __syncthreads();
#pragma unroll
    for (int i = 0; i < 4; i++) {
        float v = t[tx][ty + 8 * i];
        __nv_bfloat16 hb = __float2bfloat16(v);
        __nv_bfloat16 lb = __float2bfloat16(v - __bfloat162float(hb));
        size_t off = (size_t)(kvh * HD + d0 + ty + 8 * i) * KV_PAD + kv0 + tx;
        g_vthi[off] = hb; g_vtlo[off] = lb;
    }
}

// ---------------- RMS norm fp32 -> bf16 hi/lo ----------------
__global__ void rmsnorm_split(const float* __restrict__ x, const float* __restrict__ w,
                              __nv_bfloat16* __restrict__ hi, __nv_bfloat16* __restrict__ lo,
                              int nrows, int nheads, int ld_in, int ld_out)
{
    int gw = (int)((blockIdx.x * blockDim.x + threadIdx.x) >> 5);
    int lane = threadIdx.x & 31;
    if (gw >= nrows * nheads) return;
    int row = gw / nheads, h = gw - row * nheads;
    const float* p = x + (size_t)row * ld_in + h * HD;
    float4 v = *(const float4*)(p + lane * 4);
    float ss = v.x * v.x + v.y * v.y + v.z * v.z + v.w * v.w;
#pragma unroll
    for (int o = 16; o > 0; o >>= 1) ss += __shfl_xor_sync(0xffffffffu, ss, o);
    float s = rsqrtf(ss * (1.f / HD) + 1e-5f);
    float4 wv = *(const float4*)(w + lane * 4);
    v.x *= s * wv.x; v.y *= s * wv.y; v.z *= s * wv.z; v.w *= s * wv.w;
    uint2 uh, ul;
    split2(v.x, v.y, uh.x, ul.x);
    split2(v.z, v.w, uh.y, ul.y);
    size_t off = (size_t)row * ld_out + h * HD + lane * 4;
    *(uint2*)(hi + off) = uh;
    *(uint2*)(lo + off) = ul;
}

// ---------------- flash attention: cp.async K/V pipeline + LDSM frags --------
#define AQST 136
#define AVST 72
#define AQH_OFF 0
#define AQL_OFF 34816
#define AK_OFF  69632
#define AK_SS   34816
#define AV_OFF  139264
#define AV_SS   36864
#define ATTN_SMEM 212992
#define NCHUNK  (KV_PAD / 64)

__global__ void __launch_bounds__(256, 1) attn_mma(const float* __restrict__ mask)
{
    extern __shared__ char sma[];
    const uint32_t sb = smem_u32(sma);
    const int tid = threadIdx.x, warp = tid >> 5, lane = tid & 31;
    const int g = lane >> 2, tig = lane & 3;
    const int h = blockIdx.y, kvh = h >> 2;
    const int q0 = blockIdx.x * 128;
    const int wr = warp * 16;
    const int row0 = q0 + wr + g;

    const int a_row_in = lane & 15;
    const int a_ckb    = lane >> 4;
    const int b_row_in = (((lane >> 4) & 1) << 3) + (lane & 7);
    const int b_ckb    = (lane >> 3) & 1;

    __nv_bfloat16* Qh = (__nv_bfloat16*)(sma + AQH_OFF);
    __nv_bfloat16* Ql = (__nv_bfloat16*)(sma + AQL_OFF);

#pragma unroll
    for (int it = 0; it < 8; it++) {
        int idx = tid + it * 256;
        int r = idx >> 4, c = (idx & 15) * 8;
        size_t off = (size_t)(q0 + r) * HIDDEN + h * HD + c;
        *(uint4*)&Qh[r * AQST + c] = *(const uint4*)(g_qhi + off);
        *(uint4*)&Ql[r * AQST + c] = *(const uint4*)(g_qlo + off);
    }

    auto load_kv = [&](int ck, int st) {
        const int kv0 = ck * 64;
        const uint32_t kb = sb + AK_OFF + st * AK_SS;
        const uint32_t vb = sb + AV_OFF + st * AV_SS;
#pragma unroll
        for (int i = 0; i < 4; i++) {
            int idx = tid + i * 256;
            int r = idx >> 4, c = idx & 15;
            uint32_t soff = (uint32_t)(r * 272 + c * 16);
            int ok = (kv0 + r < KV_LEN) ? 16 : 0;
            int rc = (kv0 + r < KV_LEN) ? (kv0 + r) : 0;
            size_t goff = (size_t)rc * (NKVH * HD) + kvh * HD + c * 8;
            CP16(kb + soff, g_khi + goff, ok);
            CP16(kb + 17408 + soff, g_klo + goff, ok);
        }
#pragma unroll
        for (int i = 0; i < 4; i++) {
            int idx = tid + i * 256;
            int d = idx >> 3, c = idx & 7;
            uint32_t soff = (uint32_t)(d * 144 + c * 16);
            size_t goff = ((size_t)kvh * HD + d) * KV_PAD + kv0 + c * 8;
            CP16(vb + soff, g_vthi + goff, 16);
            CP16(vb + 18432 + soff, g_vtlo + goff, 16);
        }
    };

    float o[16][4];
#pragma unroll
    for (int n = 0; n < 16; n++)
#pragma unroll
        for (int t = 0; t < 4; t++) o[n][t] = 0.f;
    float m0 = -1e30f, m1 = -1e30f, l0 = 0.f, l1 = 0.f;

    load_kv(0, 0);
    CP_COMMIT();

    for (int ck = 0; ck < NCHUNK; ck++) {
        const int kv0 = ck * 64;
        const int st = ck & 1;
        if (ck + 1 < NCHUNK) load_kv(ck + 1, st ^ 1);
        CP_COMMIT();
        CP_WAIT1();
        __syncthreads();

        const uint32_t kbh = sb + AK_OFF + st * AK_SS;
        const uint32_t vbh = sb + AV_OFF + st * AV_SS;

        bool partial = (kv0 + 64 > KV_LEN);
        // ---- mask prefetch (non-partial fast path) ----
        float mk[8][4];
        if (!partial) {
#pragma unroll
            for (int j = 0; j < 8; j++) {
                int col = kv0 + 8 * j + tig * 2;
                const float* mp = mask + (size_t)row0 * KV_LEN + col;
                float2 a = *(const float2*)mp;
                float2 b = *(const float2*)(mp + (size_t)8 * KV_LEN);
                mk[j][0] = a.x; mk[j][1] = a.y; mk[j][2] = b.x; mk[j][3] = b.y;
            }
        }

        // ---- S = Q K^T (LDSM fragments) ----
        float s[8][4];
#pragma unroll
        for (int j = 0; j < 8; j++)
#pragma unroll
            for (int c = 0; c < 4; c++) s[j][c] = 0.f;

#pragma unroll
        for (int kt = 0; kt < 8; kt++) {
            unsigned ah[4], al[4];
            uint32_t qaddr = sb + (uint32_t)((wr + a_row_in) * 272 + kt * 32 + a_ckb * 16);
            LDSM4(ah, qaddr);
            LDSM4(al, qaddr + 34816);
#pragma unroll
            for (int p = 0; p < 4; p++) {
                unsigned kf[4], kl[4], b2[2];
                uint32_t kaddr = kbh + (uint32_t)((16 * p + b_row_in) * 272
                                                  + kt * 32 + b_ckb * 16);
                LDSM4(kf, kaddr);
                LDSM4(kl, kaddr + 17408);
                b2[0] = kf[0]; b2[1] = kf[1];
                MMA_BF16(s[2 * p], ah, b2);
                MMA_BF16(s[2 * p], al, b2);
                b2[0] = kf[2]; b2[1] = kf[3];
                MMA_BF16(s[2 * p + 1], ah, b2);
                MMA_BF16(s[2 * p + 1], al, b2);
                b2[0] = kl[0]; b2[1] = kl[1];
                MMA_BF16(s[2 * p], ah, b2);
                b2[0] = kl[2]; b2[1] = kl[3];
                MMA_BF16(s[2 * p + 1], ah, b2);
            }
        }

        // ---- scale + mask + softmax ----
        float rmax0 = -1e30f, rmax1 = -1e30f;
        if (!partial) {
#pragma unroll
            for (int j = 0; j < 8; j++) {
                s[j][0] = fmaf(s[j][0], ATTN_SCALE, mk[j][0]);
                s[j][1] = fmaf(s[j][1], ATTN_SCALE, mk[j][1]);
                s[j][2] = fmaf(s[j][2], ATTN_SCALE, mk[j][2]);
                s[j][3] = fmaf(s[j][3], ATTN_SCALE, mk[j][3]);
                rmax0 = fmaxf(rmax0, fmaxf(s[j][0], s[j][1]));
                rmax1 = fmaxf(rmax1, fmaxf(s[j][2], s[j][3]));
            }
        } else {
#pragma unroll
            for (int j = 0; j < 8; j++) {
#pragma unroll
                for (int c = 0; c < 2; c++) {
                    int col = kv0 + 8 * j + tig * 2 + c;
                    if (col < KV_LEN) {
                        s[j][c]     = fmaf(s[j][c], ATTN_SCALE,
                                           mask[(size_t)row0 * KV_LEN + col]);
                        s[j][2 + c] = fmaf(s[j][2 + c], ATTN_SCALE,
                                           mask[(size_t)(row0 + 8) * KV_LEN + col]);
                    } else {
                        s[j][c] = -1e30f;
                        s[j][2 + c] = -1e30f;
                    }
                }
                rmax0 = fmaxf(rmax0, fmaxf(s[j][0], s[j][1]));
                rmax1 = fmaxf(rmax1, fmaxf(s[j][2], s[j][3]));
            }
        }
        rmax0 = fmaxf(rmax0, __shfl_xor_sync(0xffffffffu, rmax0, 1));
        rmax0 = fmaxf(rmax0, __shfl_xor_sync(0xffffffffu, rmax0, 2));
        rmax1 = fmaxf(rmax1, __shfl_xor_sync(0xffffffffu, rmax1, 1));
        rmax1 = fmaxf(rmax1, __shfl_xor_sync(0xffffffffu, rmax1, 2));

        float mn0 = fmaxf(m0, rmax0), mn1 = fmaxf(m1, rmax1);
        float f0 = __expf(m0 - mn0), f1 = __expf(m1 - mn1);
        m0 = mn0; m1 = mn1;

        float sum0 = 0.f, sum1 = 0.f;
#pragma unroll
        for (int j = 0; j < 8; j++) {
            s[j][0] = __expf(s[j][0] - mn0);
            s[j][1] = __expf(s[j][1] - mn0);
            s[j][2] = __expf(s[j][2] - mn1);
            s[j][3] = __expf(s[j][3] - mn1);
            sum0 += s[j][0] + s[j][1];
            sum1 += s[j][2] + s[j][3];
        }
        sum0 += __shfl_xor_sync(0xffffffffu, sum0, 1);
        sum0 += __shfl_xor_sync(0xffffffffu, sum0, 2);
        sum1 += __shfl_xor_sync(0xffffffffu, sum1, 1);
        sum1 += __shfl_xor_sync(0xffffffffu, sum1, 2);
        l0 = l0 * f0 + sum0;
        l1 = l1 * f1 + sum1;

#pragma unroll
        for (int n = 0; n < 16; n++) {
            o[n][0] *= f0; o[n][1] *= f0; o[n][2] *= f1; o[n][3] *= f1;
        }

        // ---- PV (LDSM V fragments) ----
#pragma unroll
        for (int t = 0; t < 4; t++) {
            unsigned ph[4], pl[4];
            split2(s[2 * t][0],     s[2 * t][1],     ph[0], pl[0]);
            split2(s[2 * t][2],     s[2 * t][3],     ph[1], pl[1]);
            split2(s[2 * t + 1][0], s[2 * t + 1][1], ph[2], pl[2]);
            split2(s[2 * t + 1][2], s[2 * t + 1][3], ph[3], pl[3]);
#pragma unroll
            for (int p = 0; p < 8; p++) {
                unsigned vf[4], vl4[4], b2[2];
                uint32_t vaddr = vbh + (uint32_t)((16 * p + b_row_in) * 144
                                                  + t * 32 + b_ckb * 16);
                LDSM4(vf, vaddr);
                LDSM4(vl4, vaddr + 18432);
                b2[0] = vf[0]; b2[1] = vf[1];
                MMA_BF16(o[2 * p], ph, b2);
                MMA_BF16(o[2 * p], pl, b2);
                b2[0] = vf[2]; b2[1] = vf[3];
                MMA_BF16(o[2 * p + 1], ph, b2);
                MMA_BF16(o[2 * p + 1], pl, b2);
                b2[0] = vl4[0]; b2[1] = vl4[1];
                MMA_BF16(o[2 * p], ph, b2);
                b2[0] = vl4[2]; b2[1] = vl4[3];
                MMA_BF16(o[2 * p + 1], ph, b2);
            }
        }
        __syncthreads();
    }

    float il0 = 1.f / l0, il1 = 1.f / l1;
#pragma unroll
    for (int n = 0; n < 16; n++) {
        unsigned h01, lo01, h23, lo23;
        split2(o[n][0] * il0, o[n][1] * il0, h01, lo01);
        split2(o[n][2] * il1, o[n][3] * il1, h23, lo23);
        size_t base = (size_t)row0 * HIDDEN + h * HD + 8 * n + tig * 2;
        *(unsigned*)(g_attnhi + base) = h01;
        *(unsigned*)(g_attnlo + base) = lo01;
        *(unsigned*)(g_attnhi + base + (size_t)8 * HIDDEN) = h23;
        *(unsigned*)(g_attnlo + base + (size_t)8 * HIDDEN) = lo23;
    }
}

// ---------------------------------------------------------------------------
extern "C" void kernel_launch(void* const* d_in, const int* in_sizes, int n_in,
                              void* d_out, int out_size)
{
    const float* hidden = (const float*)d_in[0];
    const float* cross  = (const float*)d_in[1];
    const float* mask   = (const float*)d_in[2];
    const float* w_qkv  = (const float*)d_in[3];
    const float* w_o    = (const float*)d_in[4];
    const float* q_norm = (const float*)d_in[5];
    const float* k_norm = (const float*)d_in[6];
    float* out = (float*)d_out;
    (void)in_sizes; (void)n_in; (void)out_size;

    float *pq, *pkv;
    cudaGetSymbolAddress((void**)&pq,  g_q);
    cudaGetSymbolAddress((void**)&pkv, g_kv);
    __nv_bfloat16 *hid_hi, *hid_lo, *cross_hi, *cross_lo;
    __nv_bfloat16 *wqkvT_hi, *wqkvT_lo, *woT_hi, *woT_lo;
    __nv_bfloat16 *qhi, *qlo, *khi, *klo, *attnhi, *attnlo;
    cudaGetSymbolAddress((void**)&hid_hi,   g_hid_hi);
    cudaGetSymbolAddress((void**)&hid_lo,   g_hid_lo);
    cudaGetSymbolAddress((void**)&cross_hi, g_cross_hi);
    cudaGetSymbolAddress((void**)&cross_lo, g_cross_lo);
    cudaGetSymbolAddress((void**)&wqkvT_hi, g_wqkvT_hi);
    cudaGetSymbolAddress((void**)&wqkvT_lo, g_wqkvT_lo);
    cudaGetSymbolAddress((void**)&woT_hi,   g_woT_hi);
    cudaGetSymbolAddress((void**)&woT_lo,   g_woT_lo);
    cudaGetSymbolAddress((void**)&qhi,      g_qhi);
    cudaGetSymbolAddress((void**)&qlo,      g_qlo);
    cudaGetSymbolAddress((void**)&khi,      g_khi);
    cudaGetSymbolAddress((void**)&klo,      g_klo);
    cudaGetSymbolAddress((void**)&attnhi,   g_attnhi);
    cudaGetSymbolAddress((void**)&attnlo,   g_attnlo);

    // 1) fused activation split
    {
        int n4 = (Q_LEN + KV_LEN) * HIDDEN / 4;
        split_acts<<<(n4 + 255) / 256, 256>>>(hidden, cross);
    }
    // 2,3) weight transpose + split
    wtrans_split<<<dim3(QKV_LDB / 32, HIDDEN / 32), dim3(32, 8)>>>(
        w_qkv, wqkvT_hi, wqkvT_lo, HIDDEN, QKV_LDB);
    wtrans_split<<<dim3(HIDDEN / 32, HIDDEN / 32), dim3(32, 8)>>>(
        w_o, woT_hi, woT_lo, HIDDEN, HIDDEN);

    cudaFuncSetAttribute(gemm_bf16x3, cudaFuncAttributeMaxDynamicSharedMemorySize,
                         GB_SMEM);

    // 4) KV projection: M=6404, N=2048
    gemm_bf16x3<<<dim3(KV_N / 256, (KV_LEN + 127) / 128), 256, GB_SMEM>>>(
        cross_hi, cross_lo,
        wqkvT_hi + (size_t)(NH * HD) * HIDDEN, wqkvT_lo + (size_t)(NH * HD) * HIDDEN,
        pkv, KV_LEN, KV_N);
    // 5) Q projection: M=1024, N=4096
    gemm_bf16x3<<<dim3(HIDDEN / 256, Q_LEN / 128), 256, GB_SMEM>>>(
        hid_hi, hid_lo, wqkvT_hi, wqkvT_lo, pq, Q_LEN, HIDDEN);

    // 6,7) RMS norms -> bf16 hi/lo
    {
        int nwarps = Q_LEN * NH;
        rmsnorm_split<<<(nwarps * 32 + 255) / 256, 256>>>(
            pq, q_norm, qhi, qlo, Q_LEN, NH, HIDDEN, HIDDEN);
        nwarps = KV_LEN * NKVH;
        rmsnorm_split<<<(nwarps * 32 + 255) / 256, 256>>>(
            pkv, k_norm, khi, klo, KV_LEN, NKVH, KV_N, NKVH * HD);
    }
    // 8) V transpose + split
    vtrans_split<<<dim3(KV_PAD / 32, HD / 32, NKVH), dim3(32, 8)>>>(pkv);

    // 9) attention
    cudaFuncSetAttribute(attn_mma, cudaFuncAttributeMaxDynamicSharedMemorySize,
                         ATTN_SMEM);
    attn_mma<<<dim3(Q_LEN / 128, NH), 256, ATTN_SMEM>>>(mask);

    // 10) O projection: M=1024, N=4096
    gemm_bf16x3<<<dim3(HIDDEN / 256, Q_LEN / 128), 256, GB_SMEM>>>(
        attnhi, attnlo, woT_hi, woT_lo, out, Q_LEN, HIDDEN);
}

// round 15
// speedup vs baseline: 1.0176x; 1.0176x over previous
#include <cuda_runtime.h>
#include <cuda_bf16.h>
#include <stdint.h>
#include <math.h>

#define Q_LEN   1024
#define KV_LEN  6404
#define KV_PAD  6464
#define HIDDEN  4096
#define NH      32
#define NKVH    8
#define HD      128
#define QKV_LDB 6144
#define KV_N    2048
#define ATTN_SCALE 0.08838834764831845f

// ---------------- scratch ----------------
__device__ float g_q[Q_LEN * HIDDEN];
__device__ float g_kv[KV_LEN * KV_N];

__device__ __nv_bfloat16 g_hid_hi[Q_LEN * HIDDEN];
__device__ __nv_bfloat16 g_hid_lo[Q_LEN * HIDDEN];
__device__ __nv_bfloat16 g_cross_hi[KV_LEN * HIDDEN];
__device__ __nv_bfloat16 g_cross_lo[KV_LEN * HIDDEN];
__device__ __nv_bfloat16 g_wqkvT_hi[QKV_LDB * HIDDEN];
__device__ __nv_bfloat16 g_wqkvT_lo[QKV_LDB * HIDDEN];
__device__ __nv_bfloat16 g_woT_hi[HIDDEN * HIDDEN];
__device__ __nv_bfloat16 g_woT_lo[HIDDEN * HIDDEN];
__device__ __nv_bfloat16 g_qhi[Q_LEN * HIDDEN];
__device__ __nv_bfloat16 g_qlo[Q_LEN * HIDDEN];
__device__ __nv_bfloat16 g_khi[KV_LEN * (NKVH * HD)];
__device__ __nv_bfloat16 g_klo[KV_LEN * (NKVH * HD)];
__device__ __nv_bfloat16 g_vthi[NKVH * HD * KV_PAD];
__device__ __nv_bfloat16 g_vtlo[NKVH * HD * KV_PAD];
__device__ __nv_bfloat16 g_attnhi[Q_LEN * HIDDEN];
__device__ __nv_bfloat16 g_attnlo[Q_LEN * HIDDEN];

__device__ __forceinline__ void split2(float x, float y, unsigned& hi, unsigned& lo)
{
    __nv_bfloat16 hx = __float2bfloat16(x), hy = __float2bfloat16(y);
    float lx = x - __bfloat162float(hx), ly = y - __bfloat162float(hy);
    __nv_bfloat16 lxb = __float2bfloat16(lx), lyb = __float2bfloat16(ly);
    hi = (unsigned)__bfloat16_as_ushort(hx) | ((unsigned)__bfloat16_as_ushort(hy) << 16);
    lo = (unsigned)__bfloat16_as_ushort(lxb) | ((unsigned)__bfloat16_as_ushort(lyb) << 16);
}

__device__ __forceinline__ uint32_t smem_u32(const void* p)
{
    uint32_t a;
    asm("{ .reg .u64 t; cvta.to.shared.u64 t, %1; cvt.u32.u64 %0, t; }"
        : "=r"(a) : "l"(p));
    return a;
}
#define CP16(dst, src, n) \
    asm volatile("cp.async.cg.shared.global [%0], [%1], 16, %2;" \
                 :: "r"(dst), "l"(src), "r"(n))
#define CP_COMMIT() asm volatile("cp.async.commit_group;" ::: "memory")
#define CP_WAIT1()  asm volatile("cp.async.wait_group 1;" ::: "memory")

#define MMA_BF16(d, a, b)                                                      \
    asm volatile(                                                              \
        "mma.sync.aligned.m16n8k16.row.col.f32.bf16.bf16.f32 "                 \
        "{%0,%1,%2,%3},{%4,%5,%6,%7},{%8,%9},{%0,%1,%2,%3};"                   \
        : "+f"((d)[0]), "+f"((d)[1]), "+f"((d)[2]), "+f"((d)[3])               \
        : "r"((a)[0]), "r"((a)[1]), "r"((a)[2]), "r"((a)[3]),                  \
          "r"((b)[0]), "r"((b)[1]))

#define LDSM4(r, addr)                                                         \
    asm volatile(                                                              \
        "ldmatrix.sync.aligned.m8n8.x4.shared.b16 {%0,%1,%2,%3}, [%4];"        \
        : "=r"((r)[0]), "=r"((r)[1]), "=r"((r)[2]), "=r"((r)[3])               \
        : "r"(addr))

// ---------------- bf16x3 GEMM, block 128x256 (R12, unchanged) ----------------
#define GA_BUF   (128 * 128)
#define GBB_BUF  (256 * 128)
#define GS_AH    0
#define GS_AL    GA_BUF
#define GS_BH    (2 * GA_BUF)
#define GS_BL    (2 * GA_BUF + GBB_BUF)
#define GB_STAGE (2 * GA_BUF + 2 * GBB_BUF)
#define GB_SMEM  (2 * GB_STAGE)

__global__ void __launch_bounds__(256, 1) gemm_bf16x3(
    const __nv_bfloat16* __restrict__ Ahi, const __nv_bfloat16* __restrict__ Alo,
    const __nv_bfloat16* __restrict__ Bthi, const __nv_bfloat16* __restrict__ Btlo,
    float* __restrict__ C, int M, int ldc)
{
    extern __shared__ char smg[];
    const uint32_t sb = smem_u32(smg);
    const int tid  = threadIdx.x;
    const int warp = tid >> 5, lane = tid & 31;
    const int g = lane >> 2, tig = lane & 3;
    const int wm = warp & 1, wn = warp >> 1;
    const int row0 = blockIdx.y * 128, col0 = blockIdx.x * 256;
    const int rowbase = wm * 64, colbase = wn * 64;
    const int K = HIDDEN;
    const int nck = K / 64;

    const int a_row_in = lane & 15;
    const int a_ckb    = lane >> 4;
    const int b_row_in = (((lane >> 4) & 1) << 3) + (lane & 7);
    const int b_ckb    = (lane >> 3) & 1;

    float acc[4][8][4];
#pragma unroll
    for (int i = 0; i < 4; i++)
#pragma unroll
        for (int j = 0; j < 8; j++)
#pragma unroll
            for (int t = 0; t < 4; t++) acc[i][j][t] = 0.f;

    auto load_chunk = [&](int ck, int st) {
        const uint32_t stb = sb + st * GB_STAGE;
        const int k0 = ck * 64;
#pragma unroll
        for (int i = 0; i < 4; i++) {
            int idx = tid + i * 256;
            int r = idx >> 3, c = idx & 7;
            uint32_t soff = (uint32_t)(r * 128 + ((c ^ (r & 7)) * 16));
            int gr = row0 + r;
            int ok = (gr < M) ? 16 : 0;
            int grc = (gr < M) ? gr : 0;
            size_t aoff = (size_t)grc * K + k0 + c * 8;
            CP16(stb + GS_AH + soff, Ahi + aoff, ok);
            CP16(stb + GS_AL + soff, Alo + aoff, ok);
        }
#pragma unroll
        for (int i = 0; i < 8; i++) {
            int idx = tid + i * 256;
            int r = idx >> 3, c = idx & 7;
            uint32_t soff = (uint32_t)(r * 128 + ((c ^ (r & 7)) * 16));
            size_t boff = (size_t)(col0 + r) * K + k0 + c * 8;
            CP16(stb + GS_BH + soff, Bthi + boff, 16);
            CP16(stb + GS_BL + soff, Btlo + boff, 16);
        }
    };

    load_chunk(0, 0);
    CP_COMMIT();

    for (int ck = 0; ck < nck; ck++) {
        const int st = ck & 1;
        if (ck + 1 < nck) load_chunk(ck + 1, st ^ 1);
        CP_COMMIT();
        CP_WAIT1();
        __syncthreads();

        const uint32_t stb = sb + st * GB_STAGE;

#pragma unroll
        for (int ks = 0; ks < 4; ks++) {
            unsigned ah[4][4], al[4][4], bb[8][2], bfr[4];
#pragma unroll
            for (int am = 0; am < 4; am++) {
                int row = rowbase + am * 16 + a_row_in;
                int ck4 = (2 * ks + a_ckb) ^ (row & 7);
                uint32_t addr = stb + (uint32_t)(row * 128 + ck4 * 16);
                LDSM4(ah[am], addr);
                LDSM4(al[am], addr + GA_BUF);
            }
#pragma unroll
            for (int p = 0; p < 4; p++) {
                int row = colbase + p * 16 + b_row_in;
                int ck4 = (2 * ks + b_ckb) ^ (row & 7);
                uint32_t addr = stb + GS_BH + (uint32_t)(row * 128 + ck4 * 16);
                LDSM4(bfr, addr);
                bb[2 * p][0] = bfr[0]; bb[2 * p][1] = bfr[1];
                bb[2 * p + 1][0] = bfr[2]; bb[2 * p + 1][1] = bfr[3];
            }
#pragma unroll
            for (int am = 0; am < 4; am++)
#pragma unroll
                for (int an = 0; an < 8; an++) MMA_BF16(acc[am][an], ah[am], bb[an]);
#pragma unroll
            for (int am = 0; am < 4; am++)
#pragma unroll
                for (int an = 0; an < 8; an++) MMA_BF16(acc[am][an], al[am], bb[an]);
#pragma unroll
            for (int p = 0; p < 4; p++) {
                int row = colbase + p * 16 + b_row_in;
                int ck4 = (2 * ks + b_ckb) ^ (row & 7);
                uint32_t addr = stb + GS_BL + (uint32_t)(row * 128 + ck4 * 16);
                LDSM4(bfr, addr);
                bb[2 * p][0] = bfr[0]; bb[2 * p][1] = bfr[1];
                bb[2 * p + 1][0] = bfr[2]; bb[2 * p + 1][1] = bfr[3];
            }
#pragma unroll
            for (int am = 0; am < 4; am++)
#pragma unroll
                for (int an = 0; an < 8; an++) MMA_BF16(acc[am][an], ah[am], bb[an]);
        }
        __syncthreads();
    }

#pragma unroll
    for (int am = 0; am < 4; am++) {
#pragma unroll
        for (int an = 0; an < 8; an++) {
            int r = row0 + rowbase + am * 16 + g;
            int c = col0 + colbase + an * 8 + tig * 2;
            if (r < M)
                *(float2*)(C + (size_t)r * ldc + c) =
                    make_float2(acc[am][an][0], acc[am][an][1]);
            if (r + 8 < M)
                *(float2*)(C + (size_t)(r + 8) * ldc + c) =
                    make_float2(acc[am][an][2], acc[am][an][3]);
        }
    }
}

// ---------------- fused activation split ----------------
__global__ void split_acts(const float* __restrict__ hid, const float* __restrict__ cross)
{
    const int nh = Q_LEN * HIDDEN / 4;
    const int nc = KV_LEN * HIDDEN / 4;
    int i = blockIdx.x * blockDim.x + threadIdx.x;
    if (i >= nh + nc) return;
    const float4* src;
    __nv_bfloat16 *hi, *lo;
    int j;
    if (i < nh) { src = (const float4*)hid;   hi = g_hid_hi;   lo = g_hid_lo;   j = i; }
    else        { src = (const float4*)cross; hi = g_cross_hi; lo = g_cross_lo; j = i - nh; }
    float4 v = src[j];
    uint2 uh, ul;
    split2(v.x, v.y, uh.x, ul.x);
    split2(v.z, v.w, uh.y, ul.y);
    ((uint2*)hi)[j] = uh;
    ((uint2*)lo)[j] = ul;
}

// ---------------- fp32 [R][C] -> bf16 hi/lo [C][R] ----------------
__global__ void wtrans_split(const float* __restrict__ w,
                             __nv_bfloat16* __restrict__ hi,
                             __nv_bfloat16* __restrict__ lo, int R, int C)
{
    __shared__ float t[32][33];
    int tx = threadIdx.x, ty = threadIdx.y;
    int r0 = blockIdx.y * 32, c0 = blockIdx.x * 32;
#pragma unroll
    for (int i = 0; i < 4; i++)
        t[ty + 8 * i][tx] = w[(size_t)(r0 + ty + 8 * i) * C + c0 + tx];
    __syncthreads();
#pragma unroll
    for (int i = 0; i < 4; i++) {
        float v = t[tx][ty + 8 * i];
        __nv_bfloat16 hb = __float2bfloat16(v);
        __nv_bfloat16 lb = __float2bfloat16(v - __bfloat162float(hb));
        size_t off = (size_t)(c0 + ty + 8 * i) * R + r0 + tx;
        hi[off] = hb; lo[off] = lb;
    }
}

// ---------------- V transpose+split ----------------
__global__ void vtrans_split(const float* __restrict__ kv)
{
    __shared__ float t[32][33];
    int tx = threadIdx.x, ty = threadIdx.y;
    int kv0 = blockIdx.x * 32, d0 = blockIdx.y * 32, kvh = blockIdx.z;
#pragma unroll
    for (int i = 0; i < 4; i++) {
        int r = kv0 + ty + 8 * i;
        t[ty + 8 * i][tx] = (r < KV_LEN)
            ? kv[(size_t)r * KV_N + NKVH * HD + kvh * HD + d0 + tx] : 0.f;
    }
    __syncthreads();
#pragma unroll
    for (int i = 0; i < 4; i++) {
        float v = t[tx][ty + 8 * i];
        __nv_bfloat16 hb = __float2bfloat16(v);
        __nv_bfloat16 lb = __float2bfloat16(v - __bfloat162float(hb));
        size_t off = (size_t)(kvh * HD + d0 + ty + 8 * i) * KV_PAD + kv0 + tx;
        g_vthi[off] = hb; g_vtlo[off] = lb;
    }
}

// ---------------- RMS norm fp32 -> bf16 hi/lo ----------------
__global__ void rmsnorm_split(const float* __restrict__ x, const float* __restrict__ w,
                              __nv_bfloat16* __restrict__ hi, __nv_bfloat16* __restrict__ lo,
                              int nrows, int nheads, int ld_in, int ld_out)
{
    int gw = (int)((blockIdx.x * blockDim.x + threadIdx.x) >> 5);
    int lane = threadIdx.x & 31;
    if (gw >= nrows * nheads) return;
    int row = gw / nheads, h = gw - row * nheads;
    const float* p = x + (size_t)row * ld_in + h * HD;
    float4 v = *(const float4*)(p + lane * 4);
    float ss = v.x * v.x + v.y * v.y + v.z * v.z + v.w * v.w;
#pragma unroll
    for (int o = 16; o > 0; o >>= 1) ss += __shfl_xor_sync(0xffffffffu, ss, o);
    float s = rsqrtf(ss * (1.f / HD) + 1e-5f);
    float4 wv = *(const float4*)(w + lane * 4);
    v.x *= s * wv.x; v.y *= s * wv.y; v.z *= s * wv.z; v.w *= s * wv.w;
    uint2 uh, ul;
    split2(v.x, v.y, uh.x, ul.x);
    split2(v.z, v.w, uh.y, ul.y);
    size_t off = (size_t)row * ld_out + h * HD + lane * 4;
    *(uint2*)(hi + off) = uh;
    *(uint2*)(lo + off) = ul;
}

// ---------------- flash attention: cp.async K/V pipeline (R12) + mask prefetch
#define AQST 136
#define AVST 72
#define AQH_OFF 0
#define AQL_OFF 34816
#define AK_OFF  69632
#define AK_SS   34816
#define AV_OFF  139264
#define AV_SS   36864
#define ATTN_SMEM 212992
#define NCHUNK  (KV_PAD / 64)

__global__ void __launch_bounds__(256, 1) attn_mma(const float* __restrict__ mask)
{
    extern __shared__ char sma[];
    const uint32_t sb = smem_u32(sma);
    const int tid = threadIdx.x, warp = tid >> 5, lane = tid & 31;
    const int g = lane >> 2, tig = lane & 3;
    const int h = blockIdx.y, kvh = h >> 2;
    const int q0 = blockIdx.x * 128;
    const int wr = warp * 16;
    const int row0 = q0 + wr + g;

    __nv_bfloat16* Qh = (__nv_bfloat16*)(sma + AQH_OFF);
    __nv_bfloat16* Ql = (__nv_bfloat16*)(sma + AQL_OFF);

#pragma unroll
    for (int it = 0; it < 8; it++) {
        int idx = tid + it * 256;
        int r = idx >> 4, c = (idx & 15) * 8;
        size_t off = (size_t)(q0 + r) * HIDDEN + h * HD + c;
        *(uint4*)&Qh[r * AQST + c] = *(const uint4*)(g_qhi + off);
        *(uint4*)&Ql[r * AQST + c] = *(const uint4*)(g_qlo + off);
    }

    auto load_kv = [&](int ck, int st) {
        const int kv0 = ck * 64;
        const uint32_t kb = sb + AK_OFF + st * AK_SS;
        const uint32_t vb = sb + AV_OFF + st * AV_SS;
#pragma unroll
        for (int i = 0; i < 4; i++) {
            int idx = tid + i * 256;
            int r = idx >> 4, c = idx & 15;
            uint32_t soff = (uint32_t)(r * 272 + c * 16);
            int ok = (kv0 + r < KV_LEN) ? 16 : 0;
            int rc = (kv0 + r < KV_LEN) ? (kv0 + r) : 0;
            size_t goff = (size_t)rc * (NKVH * HD) + kvh * HD + c * 8;
            CP16(kb + soff, g_khi + goff, ok);
            CP16(kb + 17408 + soff, g_klo + goff, ok);
        }
#pragma unroll
        for (int i = 0; i < 4; i++) {
            int idx = tid + i * 256;
            int d = idx >> 3, c = idx & 7;
            uint32_t soff = (uint32_t)(d * 144 + c * 16);
            size_t goff = ((size_t)kvh * HD + d) * KV_PAD + kv0 + c * 8;
            CP16(vb + soff, g_vthi + goff, 16);
            CP16(vb + 18432 + soff, g_vtlo + goff, 16);
        }
    };

    float o[16][4];
#pragma unroll
    for (int n = 0; n < 16; n++)
#pragma unroll
        for (int t = 0; t < 4; t++) o[n][t] = 0.f;
    float m0 = -1e30f, m1 = -1e30f, l0 = 0.f, l1 = 0.f;

    load_kv(0, 0);
    CP_COMMIT();

    for (int ck = 0; ck < NCHUNK; ck++) {
        const int kv0 = ck * 64;
        const int st = ck & 1;
        if (ck + 1 < NCHUNK) load_kv(ck + 1, st ^ 1);
        CP_COMMIT();

        bool partial = (kv0 + 64 > KV_LEN);
        // ---- mask prefetch: LDGs issued before the MMA block, consumed after
        float mk[8][4];
        if (!partial) {
#pragma unroll
            for (int j = 0; j < 8; j++) {
                int col = kv0 + 8 * j + tig * 2;
                const float* mp = mask + (size_t)row0 * KV_LEN + col;
                float2 a = *(const float2*)mp;
                float2 b = *(const float2*)(mp + (size_t)8 * KV_LEN);
                mk[j][0] = a.x; mk[j][1] = a.y; mk[j][2] = b.x; mk[j][3] = b.y;
            }
        }

        CP_WAIT1();
        __syncthreads();

        const __nv_bfloat16* Kh = (const __nv_bfloat16*)(sma + AK_OFF + st * AK_SS);
        const __nv_bfloat16* Kl = (const __nv_bfloat16*)(sma + AK_OFF + st * AK_SS + 17408);
        const __nv_bfloat16* Vh = (const __nv_bfloat16*)(sma + AV_OFF + st * AV_SS);
        const __nv_bfloat16* Vl = (const __nv_bfloat16*)(sma + AV_OFF + st * AV_SS + 18432);

        float s[8][4];
#pragma unroll
        for (int j = 0; j < 8; j++)
#pragma unroll
            for (int c = 0; c < 4; c++) s[j][c] = 0.f;

#pragma unroll
        for (int kt = 0; kt < 8; kt++) {
            int ab = (wr + g) * AQST + kt * 16 + tig * 2;
            unsigned ah[4], al[4];
            ah[0] = *(const unsigned*)&Qh[ab];
            ah[1] = *(const unsigned*)&Qh[ab + 8 * AQST];
            ah[2] = *(const unsigned*)&Qh[ab + 8];
            ah[3] = *(const unsigned*)&Qh[ab + 8 * AQST + 8];
            al[0] = *(const unsigned*)&Ql[ab];
            al[1] = *(const unsigned*)&Ql[ab + 8 * AQST];
            al[2] = *(const unsigned*)&Ql[ab + 8];
            al[3] = *(const unsigned*)&Ql[ab + 8 * AQST + 8];
#pragma unroll
            for (int j = 0; j < 8; j++) {
                int bb = (8 * j + g) * AQST + kt * 16 + tig * 2;
                unsigned bh[2], bl[2];
                bh[0] = *(const unsigned*)&Kh[bb];
                bh[1] = *(const unsigned*)&Kh[bb + 8];
                bl[0] = *(const unsigned*)&Kl[bb];
                bl[1] = *(const unsigned*)&Kl[bb + 8];
                MMA_BF16(s[j], ah, bh);
                MMA_BF16(s[j], al, bh);
                MMA_BF16(s[j], ah, bl);
            }
        }

        float rmax0 = -1e30f, rmax1 = -1e30f;
        if (!partial) {
#pragma unroll
            for (int j = 0; j < 8; j++) {
                s[j][0] = fmaf(s[j][0], ATTN_SCALE, mk[j][0]);
                s[j][1] = fmaf(s[j][1], ATTN_SCALE, mk[j][1]);
                s[j][2] = fmaf(s[j][2], ATTN_SCALE, mk[j][2]);
                s[j][3] = fmaf(s[j][3], ATTN_SCALE, mk[j][3]);
                rmax0 = fmaxf(rmax0, fmaxf(s[j][0], s[j][1]));
                rmax1 = fmaxf(rmax1, fmaxf(s[j][2], s[j][3]));
            }
        } else {
#pragma unroll
            for (int j = 0; j < 8; j++) {
#pragma unroll
                for (int c = 0; c < 2; c++) {
                    int col = kv0 + 8 * j + tig * 2 + c;
                    if (col < KV_LEN) {
                        s[j][c]     = fmaf(s[j][c], ATTN_SCALE,
                                           mask[(size_t)row0 * KV_LEN + col]);
                        s[j][2 + c] = fmaf(s[j][2 + c], ATTN_SCALE,
                                           mask[(size_t)(row0 + 8) * KV_LEN + col]);
                    } else {
                        s[j][c] = -1e30f;
                        s[j][2 + c] = -1e30f;
                    }
                }
                rmax0 = fmaxf(rmax0, fmaxf(s[j][0], s[j][1]));
                rmax1 = fmaxf(rmax1, fmaxf(s[j][2], s[j][3]));
            }
        }
        rmax0 = fmaxf(rmax0, __shfl_xor_sync(0xffffffffu, rmax0, 1));
        rmax0 = fmaxf(rmax0, __shfl_xor_sync(0xffffffffu, rmax0, 2));
        rmax1 = fmaxf(rmax1, __shfl_xor_sync(0xffffffffu, rmax1, 1));
        rmax1 = fmaxf(rmax1, __shfl_xor_sync(0xffffffffu, rmax1, 2));

        float mn0 = fmaxf(m0, rmax0), mn1 = fmaxf(m1, rmax1);
        float f0 = __expf(m0 - mn0), f1 = __expf(m1 - mn1);
        m0 = mn0; m1 = mn1;

        float sum0 = 0.f, sum1 = 0.f;
#pragma unroll
        for (int j = 0; j < 8; j++) {
            s[j][0] = __expf(s[j][0] - mn0);
            s[j][1] = __expf(s[j][1] - mn0);
            s[j][2] = __expf(s[j][2] - mn1);
            s[j][3] = __expf(s[j][3] - mn1);
            sum0 += s[j][0] + s[j][1];
            sum1 += s[j][2] + s[j][3];
        }
        sum0 += __shfl_xor_sync(0xffffffffu, sum0, 1);
        sum0 += __shfl_xor_sync(0xffffffffu, sum0, 2);
        sum1 += __shfl_xor_sync(0xffffffffu, sum1, 1);
        sum1 += __shfl_xor_sync(0xffffffffu, sum1, 2);
        l0 = l0 * f0 + sum0;
        l1 = l1 * f1 + sum1;

#pragma unroll
        for (int n = 0; n < 16; n++) {
            o[n][0] *= f0; o[n][1] *= f0; o[n][2] *= f1; o[n][3] *= f1;
        }

#pragma unroll
        for (int t = 0; t < 4; t++) {
            unsigned ph[4], pl[4];
            split2(s[2 * t][0],     s[2 * t][1],     ph[0], pl[0]);
            split2(s[2 * t][2],     s[2 * t][3],     ph[1], pl[1]);
            split2(s[2 * t + 1][0], s[2 * t + 1][1], ph[2], pl[2]);
            split2(s[2 * t + 1][2], s[2 * t + 1][3], ph[3], pl[3]);
#pragma unroll
            for (int n = 0; n < 16; n++) {
                int vb = (8 * n + g) * AVST + t * 16 + tig * 2;
                unsigned bh[2], bl[2];
                bh[0] = *(const unsigned*)&Vh[vb];
                bh[1] = *(const unsigned*)&Vh[vb + 8];
                bl[0] = *(const unsigned*)&Vl[vb];
                bl[1] = *(const unsigned*)&Vl[vb + 8];
                MMA_BF16(o[n], ph, bh);
                MMA_BF16(o[n], pl, bh);
                MMA_BF16(o[n], ph, bl);
            }
        }
        __syncthreads();
    }

    float il0 = 1.f / l0, il1 = 1.f / l1;
#pragma unroll
    for (int n = 0; n < 16; n++) {
        unsigned h01, lo01, h23, lo23;
        split2(o[n][0] * il0, o[n][1] * il0, h01, lo01);
        split2(o[n][2] * il1, o[n][3] * il1, h23, lo23);
        size_t base = (size_t)row0 * HIDDEN + h * HD + 8 * n + tig * 2;
        *(unsigned*)(g_attnhi + base) = h01;
        *(unsigned*)(g_attnlo + base) = lo01;
        *(unsigned*)(g_attnhi + base + (size_t)8 * HIDDEN) = h23;
        *(unsigned*)(g_attnlo + base + (size_t)8 * HIDDEN) = lo23;
    }
}

// ---------------------------------------------------------------------------
extern "C" void kernel_launch(void* const* d_in, const int* in_sizes, int n_in,
                              void* d_out, int out_size)
{
    const float* hidden = (const float*)d_in[0];
    const float* cross  = (const float*)d_in[1];
    const float* mask   = (const float*)d_in[2];
    const float* w_qkv  = (const float*)d_in[3];
    const float* w_o    = (const float*)d_in[4];
    const float* q_norm = (const float*)d_in[5];
    const float* k_norm = (const float*)d_in[6];
    float* out = (float*)d_out;
    (void)in_sizes; (void)n_in; (void)out_size;

    float *pq, *pkv;
    cudaGetSymbolAddress((void**)&pq,  g_q);
    cudaGetSymbolAddress((void**)&pkv, g_kv);
    __nv_bfloat16 *hid_hi, *hid_lo, *cross_hi, *cross_lo;
    __nv_bfloat16 *wqkvT_hi, *wqkvT_lo, *woT_hi, *woT_lo;
    __nv_bfloat16 *qhi, *qlo, *khi, *klo, *attnhi, *attnlo;
    cudaGetSymbolAddress((void**)&hid_hi,   g_hid_hi);
    cudaGetSymbolAddress((void**)&hid_lo,   g_hid_lo);
    cudaGetSymbolAddress((void**)&cross_hi, g_cross_hi);
    cudaGetSymbolAddress((void**)&cross_lo, g_cross_lo);
    cudaGetSymbolAddress((void**)&wqkvT_hi, g_wqkvT_hi);
    cudaGetSymbolAddress((void**)&wqkvT_lo, g_wqkvT_lo);
    cudaGetSymbolAddress((void**)&woT_hi,   g_woT_hi);
    cudaGetSymbolAddress((void**)&woT_lo,   g_woT_lo);
    cudaGetSymbolAddress((void**)&qhi,      g_qhi);
    cudaGetSymbolAddress((void**)&qlo,      g_qlo);
    cudaGetSymbolAddress((void**)&khi,      g_khi);
    cudaGetSymbolAddress((void**)&klo,      g_klo);
    cudaGetSymbolAddress((void**)&attnhi,   g_attnhi);
    cudaGetSymbolAddress((void**)&attnlo,   g_attnlo);

    // 1) fused activation split
    {
        int n4 = (Q_LEN + KV_LEN) * HIDDEN / 4;
        split_acts<<<(n4 + 255) / 256, 256>>>(hidden, cross);
    }
    // 2,3) weight transpose + split
    wtrans_split<<<dim3(QKV_LDB / 32, HIDDEN / 32), dim3(32, 8)>>>(
        w_qkv, wqkvT_hi, wqkvT_lo, HIDDEN, QKV_LDB);
    wtrans_split<<<dim3(HIDDEN / 32, HIDDEN / 32), dim3(32, 8)>>>(
        w_o, woT_hi, woT_lo, HIDDEN, HIDDEN);

    cudaFuncSetAttribute(gemm_bf16x3, cudaFuncAttributeMaxDynamicSharedMemorySize,
                         GB_SMEM);

    // 4) KV projection: M=6404, N=2048
    gemm_bf16x3<<<dim3(KV_N / 256, (KV_LEN + 127) / 128), 256, GB_SMEM>>>(
        cross_hi, cross_lo,
        wqkvT_hi + (size_t)(NH * HD) * HIDDEN, wqkvT_lo + (size_t)(NH * HD) * HIDDEN,
        pkv, KV_LEN, KV_N);
    // 5) Q projection: M=1024, N=4096
    gemm_bf16x3<<<dim3(HIDDEN / 256, Q_LEN / 128), 256, GB_SMEM>>>(
        hid_hi, hid_lo, wqkvT_hi, wqkvT_lo, pq, Q_LEN, HIDDEN);

    // 6,7) RMS norms -> bf16 hi/lo
    {
        int nwarps = Q_LEN * NH;
        rmsnorm_split<<<(nwarps * 32 + 255) / 256, 256>>>(
            pq, q_norm, qhi, qlo, Q_LEN, NH, HIDDEN, HIDDEN);
        nwarps = KV_LEN * NKVH;
        rmsnorm_split<<<(nwarps * 32 + 255) / 256, 256>>>(
            pkv, k_norm, khi, klo, KV_LEN, NKVH, KV_N, NKVH * HD);
    }
    // 8) V transpose + split
    vtrans_split<<<dim3(KV_PAD / 32, HD / 32, NKVH), dim3(32, 8)>>>(pkv);

    // 9) attention
    cudaFuncSetAttribute(attn_mma, cudaFuncAttributeMaxDynamicSharedMemorySize,
                         ATTN_SMEM);
    attn_mma<<<dim3(Q_LEN / 128, NH), 256, ATTN_SMEM>>>(mask);

    // 10) O projection: M=1024, N=4096
    gemm_bf16x3<<<dim3(HIDDEN / 256, Q_LEN / 128), 256, GB_SMEM>>>(
        attnhi, attnlo, woT_hi, woT_lo, out, Q_LEN, HIDDEN);
}